// round 15
// baseline (speedup 1.0000x reference)
#include <cuda_runtime.h>
#include <cuda_bf16.h>
#include <cstdint>

typedef unsigned int u32;
typedef unsigned long long u64;

#define F_TOTAL 256
#define H 16
#define BATCH 32768
#define GF 16                    // features per CTA
#define NGROUPS (F_TOTAL / GF)   // 16
#define TPB 128                  // 4 warps
#define MT 2                     // 32-row blocks per warp
#define ROWS_CTA (TPB * MT)      // 256
#define XSTRIDE 20               // floats; conflict-free for 8-row strided LDS

// ---- helpers ----
__device__ __forceinline__ u64 pack2(float lo, float hi) {
    u64 r;
    asm("mov.b64 %0, {%1, %2};" : "=l"(r)
        : "r"(__float_as_uint(lo)), "r"(__float_as_uint(hi)));
    return r;
}
__device__ __forceinline__ float lo32(u64 v) { return __uint_as_float((u32)v); }
__device__ __forceinline__ float hi32(u64 v) { return __uint_as_float((u32)(v >> 32)); }
// {trunc_bf16(a) -> low half, trunc_bf16(b) -> high half}
__device__ __forceinline__ u32 prmt_hi16(u32 a, u32 b) {
    u32 d;
    asm("prmt.b32 %0, %1, %2, 0x7632;" : "=r"(d) : "r"(a), "r"(b));
    return d;
}
__device__ __forceinline__ float hif(float h) {   // truncated-bf16 value as f32
    return __uint_as_float(__float_as_uint(h) & 0xffff0000u);
}

// ---- mma.sync m16n8k16 bf16 ----
__device__ __forceinline__ void mma_bias(float* d, const u32* a, uint2 b,
                                         float c0, float c1) {
    asm volatile("mma.sync.aligned.m16n8k16.row.col.f32.bf16.bf16.f32 "
        "{%0,%1,%2,%3}, {%4,%5,%6,%7}, {%8,%9}, {%10,%11,%10,%11};"
        : "=f"(d[0]), "=f"(d[1]), "=f"(d[2]), "=f"(d[3])
        : "r"(a[0]), "r"(a[1]), "r"(a[2]), "r"(a[3]),
          "r"(b.x), "r"(b.y), "f"(c0), "f"(c1));
}
__device__ __forceinline__ void mma_acc(float* d, const u32* a, uint2 b) {
    asm volatile("mma.sync.aligned.m16n8k16.row.col.f32.bf16.bf16.f32 "
        "{%0,%1,%2,%3}, {%4,%5,%6,%7}, {%8,%9}, {%0,%1,%2,%3};"
        : "+f"(d[0]), "+f"(d[1]), "+f"(d[2]), "+f"(d[3])
        : "r"(a[0]), "r"(a[1]), "r"(a[2]), "r"(a[3]),
          "r"(b.x), "r"(b.y));
}

__global__ void igann_init_kernel(float* __restrict__ out,
                                  const float* __restrict__ bias_b) {
    int i = blockIdx.x * blockDim.x + threadIdx.x;
    if (i < BATCH) out[i] = bias_b[0];
}

__global__ __launch_bounds__(TPB, 4) void igann_mma_kernel(
    const float* __restrict__ x,   // [B, F]
    const float* __restrict__ la,  // [F]
    const float* __restrict__ W1,  // [F, H]
    const float* __restrict__ b1,  // [F, H]
    const float* __restrict__ W2,  // [F, H(out j), H(in i)]
    const float* __restrict__ b2,  // [F, H]
    const float* __restrict__ W3,  // [F, H]
    const float* __restrict__ b3,  // [F]
    float* __restrict__ out)       // [B]
{
    __shared__ float sX[ROWS_CTA * XSTRIDE];   // 20 KB x tile (padded)
    __shared__ uint2 sBfrag[GF * 128];         // 16 KB B fragments
    __shared__ float4 sW1B1[GF * 8];
    __shared__ u64 sB2p[GF * 8];
    __shared__ u64 sW3p[GF * 8];
    __shared__ float sA[GF];
    __shared__ float sB3sum;

    const int tid  = threadIdx.x;
    const int lane = tid & 31;
    const int wid  = tid >> 5;
    const int f0   = blockIdx.y * GF;
    const int rowCta = blockIdx.x * ROWS_CTA;

    // ---- stage x tile: 256 rows x 16 floats, line-efficient LDG ----
    #pragma unroll
    for (int t = 0; t < 8; t++) {
        int e  = tid + t * TPB;        // 0..1023 over (row, col4)
        int r  = e >> 2;
        int c4 = e & 3;
        float4 v = *(const float4*)(x + (size_t)(rowCta + r) * F_TOTAL
                                      + f0 + 4 * c4);
        *(float4*)(sX + r * XSTRIDE + 4 * c4) = v;
    }
    // ---- stage B fragments: W2 split hi(trunc) / lo(residual, rounded bf16) ----
    #pragma unroll
    for (int t = 0; t < 16; t++) {
        int e    = tid + t * TPB;      // 0..2047
        int fi   = e >> 7;
        int kt   = (e >> 6) & 1;
        int ns   = (e >> 5) & 1;
        int ln   = e & 31;
        int n    = ns * 8 + (ln >> 2);
        int kb   = (ln & 3) * 2;
        const float* wrow = W2 + (size_t)(f0 + fi) * 256 + n * H;
        u32 pk[2];
        #pragma unroll
        for (int hh = 0; hh < 2; hh++) {
            float w0 = wrow[kb + 8 * hh];
            float w1 = wrow[kb + 8 * hh + 1];
            u32 s0, s1;
            if (kt == 0) {
                s0 = __float_as_uint(w0) >> 16;
                s1 = __float_as_uint(w1) >> 16;
            } else {
                s0 = (u32)__bfloat16_as_ushort(__float2bfloat16(w0 - hif(w0)));
                s1 = (u32)__bfloat16_as_ushort(__float2bfloat16(w1 - hif(w1)));
            }
            pk[hh] = s0 | (s1 << 16);
        }
        sBfrag[e] = make_uint2(pk[0], pk[1]);
    }
    // ---- stage W1/b1, b2/W3 pairs ----
    {
        int fi = tid >> 3, p = tid & 7, i = 2 * p;
        float4 v;
        v.x = W1[(f0 + fi) * H + i];     v.y = b1[(f0 + fi) * H + i];
        v.z = W1[(f0 + fi) * H + i + 1]; v.w = b1[(f0 + fi) * H + i + 1];
        sW1B1[fi * 8 + p] = v;
        sB2p[fi * 8 + p] = pack2(b2[(f0 + fi) * H + i], b2[(f0 + fi) * H + i + 1]);
        sW3p[fi * 8 + p] = pack2(W3[(f0 + fi) * H + i], W3[(f0 + fi) * H + i + 1]);
    }
    if (tid < GF) sA[tid] = la[f0 + tid];
    if (tid == 0) {
        float s = 0.f;
        #pragma unroll
        for (int f = 0; f < GF; f++) s += b3[f0 + f];
        sB3sum = s;
    }
    __syncthreads();

    const int qrow = lane >> 2;
    const bool reducer = (lane & 3) == 0;
    const int wbase = wid * 64 + qrow;   // + b*32 + 8*rg

    float acc[MT][4] = {{0.f, 0.f, 0.f, 0.f}, {0.f, 0.f, 0.f, 0.f}};
    float lin[MT][4] = {{0.f, 0.f, 0.f, 0.f}, {0.f, 0.f, 0.f, 0.f}};

    // unroll 4: fi literal within group -> immediate LDS offsets + cross-feature ILP
    #pragma unroll 4
    for (int fi = 0; fi < GF; fi++) {
        const float4 wbA = sW1B1[fi * 8 + (lane & 3)];
        const float4 wbB = sW1B1[fi * 8 + (lane & 3) + 4];
        const uint2 bh0 = sBfrag[fi * 128 + lane];
        const uint2 bh1 = sBfrag[fi * 128 + 32 + lane];
        const uint2 bl0 = sBfrag[fi * 128 + 64 + lane];
        const uint2 bl1 = sBfrag[fi * 128 + 96 + lane];
        const u64 b2a = sB2p[fi * 8 + (lane & 3)];
        const u64 b2b = sB2p[fi * 8 + (lane & 3) + 4];
        const u64 w3a = sW3p[fi * 8 + (lane & 3)];
        const u64 w3b = sW3p[fi * 8 + (lane & 3) + 4];
        const float w30 = lo32(w3a), w31 = hi32(w3a);
        const float w38 = lo32(w3b), w39 = hi32(w3b);
        const float aF = sA[fi];

        #pragma unroll
        for (int b = 0; b < MT; b++) {
            // x for the 4 fragment row-groups (quad-broadcast LDS)
            float xf[4];
            #pragma unroll
            for (int rg = 0; rg < 4; rg++)
                xf[rg] = sX[(wbase + b * 32 + 8 * rg) * XSTRIDE + fi];

            if (reducer) {
                #pragma unroll
                for (int rg = 0; rg < 4; rg++)
                    lin[b][rg] = fmaf(aF, xf[rg], lin[b][rg]);
            }

            // A fragments: h1 into fragment slots; residual split via truncation
            u32 ahi[2][4], alo[2][4];
            #pragma unroll
            for (int rg = 0; rg < 4; rg++) {
                float xv = xf[rg];
                float h0 = fmaxf(fmaf(xv, wbA.x, wbA.y), 0.f);
                float h1 = fmaxf(fmaf(xv, wbA.z, wbA.w), 0.f);
                float h2 = fmaxf(fmaf(xv, wbB.x, wbB.y), 0.f);
                float h3 = fmaxf(fmaf(xv, wbB.z, wbB.w), 0.f);
                float r0 = h0 - hif(h0);
                float r1 = h1 - hif(h1);
                float r2 = h2 - hif(h2);
                float r3 = h3 - hif(h3);
                int mt = rg >> 1, sl = rg & 1;
                ahi[mt][sl]     = prmt_hi16(__float_as_uint(h0), __float_as_uint(h1));
                ahi[mt][2 + sl] = prmt_hi16(__float_as_uint(h2), __float_as_uint(h3));
                alo[mt][sl]     = prmt_hi16(__float_as_uint(r0), __float_as_uint(r1));
                alo[mt][2 + sl] = prmt_hi16(__float_as_uint(r2), __float_as_uint(r3));
            }

            // D = b2 + hi*Whi + lo*Whi + hi*Wlo
            float d[2][2][4];
            #pragma unroll
            for (int mt = 0; mt < 2; mt++) {
                mma_bias(d[mt][0], ahi[mt], bh0, lo32(b2a), hi32(b2a));
                mma_acc (d[mt][0], alo[mt], bh0);
                mma_acc (d[mt][0], ahi[mt], bl0);
                mma_bias(d[mt][1], ahi[mt], bh1, lo32(b2b), hi32(b2b));
                mma_acc (d[mt][1], alo[mt], bh1);
                mma_acc (d[mt][1], ahi[mt], bl1);
            }

            // scalar epilogue: acc += relu(D) . W3
            #pragma unroll
            for (int mt = 0; mt < 2; mt++) {
                #pragma unroll
                for (int hh = 0; hh < 2; hh++) {
                    int rg = 2 * mt + hh;
                    float t = acc[b][rg];
                    t = fmaf(fmaxf(d[mt][0][2 * hh],     0.f), w30, t);
                    t = fmaf(fmaxf(d[mt][0][2 * hh + 1], 0.f), w31, t);
                    t = fmaf(fmaxf(d[mt][1][2 * hh],     0.f), w38, t);
                    t = fmaf(fmaxf(d[mt][1][2 * hh + 1], 0.f), w39, t);
                    acc[b][rg] = t;
                }
            }
        }
    }

    // ---- reduce: quad butterfly; one atomic per row ----
    const float base = sB3sum;
    #pragma unroll
    for (int b = 0; b < MT; b++) {
        #pragma unroll
        for (int rg = 0; rg < 4; rg++) {
            float s = acc[b][rg];
            s += __shfl_xor_sync(0xffffffffu, s, 1);
            s += __shfl_xor_sync(0xffffffffu, s, 2);
            if (reducer) {
                int r = rowCta + wbase + b * 32 + 8 * rg;
                atomicAdd(&out[r], s + lin[b][rg] + base);
            }
        }
    }
}

extern "C" void kernel_launch(void* const* d_in, const int* in_sizes, int n_in,
                              void* d_out, int out_size) {
    const float* x      = (const float*)d_in[0];
    const float* la     = (const float*)d_in[1];
    const float* bias_b = (const float*)d_in[2];
    const float* W1     = (const float*)d_in[3];
    const float* b1     = (const float*)d_in[4];
    const float* W2     = (const float*)d_in[5];
    const float* b2     = (const float*)d_in[6];
    const float* W3     = (const float*)d_in[7];
    const float* b3     = (const float*)d_in[8];
    float* out = (float*)d_out;

    igann_init_kernel<<<BATCH / 256, 256>>>(out, bias_b);

    dim3 grid(BATCH / ROWS_CTA, NGROUPS);
    igann_mma_kernel<<<grid, TPB>>>(x, la, W1, b1, W2, b2, W3, b3, out);
}

// round 16
// speedup vs baseline: 1.0931x; 1.0931x over previous
#include <cuda_runtime.h>
#include <cuda_bf16.h>
#include <cstdint>

typedef unsigned int u32;
typedef unsigned long long u64;

#define F_TOTAL 256
#define H 16
#define BATCH 32768
#define GF 16                    // features per CTA
#define NGROUPS (F_TOTAL / GF)   // 16
#define TPB 128                  // 4 warps
#define MT 2                     // 32-row blocks per warp
#define ROWS_CTA (TPB * MT)      // 256
#define XSTRIDE 20               // floats; conflict-free for 8-row strided LDS

// ---- helpers ----
__device__ __forceinline__ u64 pack2(float lo, float hi) {
    u64 r;
    asm("mov.b64 %0, {%1, %2};" : "=l"(r)
        : "r"(__float_as_uint(lo)), "r"(__float_as_uint(hi)));
    return r;
}
__device__ __forceinline__ float lo32(u64 v) { return __uint_as_float((u32)v); }
__device__ __forceinline__ float hi32(u64 v) { return __uint_as_float((u32)(v >> 32)); }
// {trunc_bf16(a) -> low half, trunc_bf16(b) -> high half}
__device__ __forceinline__ u32 prmt_hi16(u32 a, u32 b) {
    u32 d;
    asm("prmt.b32 %0, %1, %2, 0x7632;" : "=r"(d) : "r"(a), "r"(b));
    return d;
}
__device__ __forceinline__ float hif(float h) {   // truncated-bf16 value as f32
    return __uint_as_float(__float_as_uint(h) & 0xffff0000u);
}

// ---- mma.sync m16n8k16 bf16 ----
__device__ __forceinline__ void mma_bias(float* d, const u32* a, uint2 b,
                                         float c0, float c1) {
    asm volatile("mma.sync.aligned.m16n8k16.row.col.f32.bf16.bf16.f32 "
        "{%0,%1,%2,%3}, {%4,%5,%6,%7}, {%8,%9}, {%10,%11,%10,%11};"
        : "=f"(d[0]), "=f"(d[1]), "=f"(d[2]), "=f"(d[3])
        : "r"(a[0]), "r"(a[1]), "r"(a[2]), "r"(a[3]),
          "r"(b.x), "r"(b.y), "f"(c0), "f"(c1));
}
__device__ __forceinline__ void mma_acc(float* d, const u32* a, uint2 b) {
    asm volatile("mma.sync.aligned.m16n8k16.row.col.f32.bf16.bf16.f32 "
        "{%0,%1,%2,%3}, {%4,%5,%6,%7}, {%8,%9}, {%0,%1,%2,%3};"
        : "+f"(d[0]), "+f"(d[1]), "+f"(d[2]), "+f"(d[3])
        : "r"(a[0]), "r"(a[1]), "r"(a[2]), "r"(a[3]),
          "r"(b.x), "r"(b.y));
}

__global__ void igann_init_kernel(float* __restrict__ out,
                                  const float* __restrict__ bias_b) {
    int i = blockIdx.x * blockDim.x + threadIdx.x;
    if (i < BATCH) out[i] = bias_b[0];
}

__global__ __launch_bounds__(TPB, 4) void igann_mma_kernel(
    const float* __restrict__ x,   // [B, F]
    const float* __restrict__ la,  // [F]
    const float* __restrict__ W1,  // [F, H]
    const float* __restrict__ b1,  // [F, H]
    const float* __restrict__ W2,  // [F, H(out j), H(in i)]
    const float* __restrict__ b2,  // [F, H]
    const float* __restrict__ W3,  // [F, H]
    const float* __restrict__ b3,  // [F]
    float* __restrict__ out)       // [B]
{
    __shared__ float sX[ROWS_CTA * XSTRIDE];   // 20 KB x tile (padded)
    __shared__ uint2 sBfrag[GF * 128];         // 16 KB B fragments
    __shared__ float4 sW1B1[GF * 8];
    __shared__ u64 sB2p[GF * 8];
    __shared__ u64 sW3p[GF * 8];
    __shared__ float sA[GF];
    __shared__ float sB3sum;

    const int tid  = threadIdx.x;
    const int lane = tid & 31;
    const int wid  = tid >> 5;
    const int f0   = blockIdx.y * GF;
    const int rowCta = blockIdx.x * ROWS_CTA;

    // ---- stage x tile: 256 rows x 16 floats, line-efficient LDG ----
    #pragma unroll
    for (int t = 0; t < 8; t++) {
        int e  = tid + t * TPB;        // 0..1023 over (row, col4)
        int r  = e >> 2;
        int c4 = e & 3;
        float4 v = *(const float4*)(x + (size_t)(rowCta + r) * F_TOTAL
                                      + f0 + 4 * c4);
        *(float4*)(sX + r * XSTRIDE + 4 * c4) = v;
    }
    // ---- stage B fragments: W2 split hi(trunc) / lo(residual, rounded bf16) ----
    #pragma unroll
    for (int t = 0; t < 16; t++) {
        int e    = tid + t * TPB;      // 0..2047
        int fi   = e >> 7;
        int kt   = (e >> 6) & 1;
        int ns   = (e >> 5) & 1;
        int ln   = e & 31;
        int n    = ns * 8 + (ln >> 2);
        int kb   = (ln & 3) * 2;
        const float* wrow = W2 + (size_t)(f0 + fi) * 256 + n * H;
        u32 pk[2];
        #pragma unroll
        for (int hh = 0; hh < 2; hh++) {
            float w0 = wrow[kb + 8 * hh];
            float w1 = wrow[kb + 8 * hh + 1];
            u32 s0, s1;
            if (kt == 0) {
                s0 = __float_as_uint(w0) >> 16;
                s1 = __float_as_uint(w1) >> 16;
            } else {
                s0 = (u32)__bfloat16_as_ushort(__float2bfloat16(w0 - hif(w0)));
                s1 = (u32)__bfloat16_as_ushort(__float2bfloat16(w1 - hif(w1)));
            }
            pk[hh] = s0 | (s1 << 16);
        }
        sBfrag[e] = make_uint2(pk[0], pk[1]);
    }
    // ---- stage W1/b1, b2/W3 pairs ----
    {
        int fi = tid >> 3, p = tid & 7, i = 2 * p;
        float4 v;
        v.x = W1[(f0 + fi) * H + i];     v.y = b1[(f0 + fi) * H + i];
        v.z = W1[(f0 + fi) * H + i + 1]; v.w = b1[(f0 + fi) * H + i + 1];
        sW1B1[fi * 8 + p] = v;
        sB2p[fi * 8 + p] = pack2(b2[(f0 + fi) * H + i], b2[(f0 + fi) * H + i + 1]);
        sW3p[fi * 8 + p] = pack2(W3[(f0 + fi) * H + i], W3[(f0 + fi) * H + i + 1]);
    }
    if (tid < GF) sA[tid] = la[f0 + tid];
    if (tid == 0) {
        float s = 0.f;
        #pragma unroll
        for (int f = 0; f < GF; f++) s += b3[f0 + f];
        sB3sum = s;
    }
    __syncthreads();

    const int qrow = lane >> 2;
    const bool reducer = (lane & 3) == 0;
    const int wbase = wid * 64 + qrow;   // + b*32 + 8*rg

    float acc[MT][4] = {{0.f, 0.f, 0.f, 0.f}, {0.f, 0.f, 0.f, 0.f}};

    // unroll 2: one extra feature's weights live (~20 regs) fits the freed budget
    #pragma unroll 2
    for (int fi = 0; fi < GF; fi++) {
        const float4 wbA = sW1B1[fi * 8 + (lane & 3)];
        const float4 wbB = sW1B1[fi * 8 + (lane & 3) + 4];
        const uint2 bh0 = sBfrag[fi * 128 + lane];
        const uint2 bh1 = sBfrag[fi * 128 + 32 + lane];
        const uint2 bl0 = sBfrag[fi * 128 + 64 + lane];
        const uint2 bl1 = sBfrag[fi * 128 + 96 + lane];
        const u64 b2a = sB2p[fi * 8 + (lane & 3)];
        const u64 b2b = sB2p[fi * 8 + (lane & 3) + 4];
        const u64 w3a = sW3p[fi * 8 + (lane & 3)];
        const u64 w3b = sW3p[fi * 8 + (lane & 3) + 4];
        const float w30 = lo32(w3a), w31 = hi32(w3a);
        const float w38 = lo32(w3b), w39 = hi32(w3b);
        const float aF = sA[fi];

        #pragma unroll
        for (int b = 0; b < MT; b++) {
            // x for the 4 fragment row-groups (quad-broadcast LDS)
            float xf[4];
            #pragma unroll
            for (int rg = 0; rg < 4; rg++)
                xf[rg] = sX[(wbase + b * 32 + 8 * rg) * XSTRIDE + fi];

            // linear term folded into acc on the reducer lane only:
            // quad butterfly later sums lane accs, so it enters exactly once.
            if (reducer) {
                #pragma unroll
                for (int rg = 0; rg < 4; rg++)
                    acc[b][rg] = fmaf(aF, xf[rg], acc[b][rg]);
            }

            // A fragments: h1 into fragment slots; residual split via truncation
            u32 ahi[2][4], alo[2][4];
            #pragma unroll
            for (int rg = 0; rg < 4; rg++) {
                float xv = xf[rg];
                float h0 = fmaxf(fmaf(xv, wbA.x, wbA.y), 0.f);
                float h1 = fmaxf(fmaf(xv, wbA.z, wbA.w), 0.f);
                float h2 = fmaxf(fmaf(xv, wbB.x, wbB.y), 0.f);
                float h3 = fmaxf(fmaf(xv, wbB.z, wbB.w), 0.f);
                float r0 = h0 - hif(h0);
                float r1 = h1 - hif(h1);
                float r2 = h2 - hif(h2);
                float r3 = h3 - hif(h3);
                int mt = rg >> 1, sl = rg & 1;
                ahi[mt][sl]     = prmt_hi16(__float_as_uint(h0), __float_as_uint(h1));
                ahi[mt][2 + sl] = prmt_hi16(__float_as_uint(h2), __float_as_uint(h3));
                alo[mt][sl]     = prmt_hi16(__float_as_uint(r0), __float_as_uint(r1));
                alo[mt][2 + sl] = prmt_hi16(__float_as_uint(r2), __float_as_uint(r3));
            }

            // D = b2 + hi*Whi + lo*Whi + hi*Wlo
            float d[2][2][4];
            #pragma unroll
            for (int mt = 0; mt < 2; mt++) {
                mma_bias(d[mt][0], ahi[mt], bh0, lo32(b2a), hi32(b2a));
                mma_acc (d[mt][0], alo[mt], bh0);
                mma_acc (d[mt][0], ahi[mt], bl0);
                mma_bias(d[mt][1], ahi[mt], bh1, lo32(b2b), hi32(b2b));
                mma_acc (d[mt][1], alo[mt], bh1);
                mma_acc (d[mt][1], ahi[mt], bl1);
            }

            // scalar epilogue: acc += relu(D) . W3
            #pragma unroll
            for (int mt = 0; mt < 2; mt++) {
                #pragma unroll
                for (int hh = 0; hh < 2; hh++) {
                    int rg = 2 * mt + hh;
                    float t = acc[b][rg];
                    t = fmaf(fmaxf(d[mt][0][2 * hh],     0.f), w30, t);
                    t = fmaf(fmaxf(d[mt][0][2 * hh + 1], 0.f), w31, t);
                    t = fmaf(fmaxf(d[mt][1][2 * hh],     0.f), w38, t);
                    t = fmaf(fmaxf(d[mt][1][2 * hh + 1], 0.f), w39, t);
                    acc[b][rg] = t;
                }
            }
        }
    }

    // ---- reduce: quad butterfly; one atomic per row ----
    const float base = sB3sum;
    #pragma unroll
    for (int b = 0; b < MT; b++) {
        #pragma unroll
        for (int rg = 0; rg < 4; rg++) {
            float s = acc[b][rg];
            s += __shfl_xor_sync(0xffffffffu, s, 1);
            s += __shfl_xor_sync(0xffffffffu, s, 2);
            if (reducer) {
                int r = rowCta + wbase + b * 32 + 8 * rg;
                atomicAdd(&out[r], s + base);
            }
        }
    }
}

extern "C" void kernel_launch(void* const* d_in, const int* in_sizes, int n_in,
                              void* d_out, int out_size) {
    const float* x      = (const float*)d_in[0];
    const float* la     = (const float*)d_in[1];
    const float* bias_b = (const float*)d_in[2];
    const float* W1     = (const float*)d_in[3];
    const float* b1     = (const float*)d_in[4];
    const float* W2     = (const float*)d_in[5];
    const float* b2     = (const float*)d_in[6];
    const float* W3     = (const float*)d_in[7];
    const float* b3     = (const float*)d_in[8];
    float* out = (float*)d_out;

    igann_init_kernel<<<BATCH / 256, 256>>>(out, bias_b);

    dim3 grid(BATCH / ROWS_CTA, NGROUPS);
    igann_mma_kernel<<<grid, TPB>>>(x, la, W1, b1, W2, b2, W3, b3, out);
}